// round 17
// baseline (speedup 1.0000x reference)
#include <cuda_runtime.h>

#define NB 2
#define NC 64
#define D  64
#define NVOX (D*D*D)            // 262144
#define NCH  (NB*NC)            // 128
#define TOT  (NCH*NVOX)         // 33554432

#define FIX_T   0.02f
#define MAXFIX  (1<<22)

#define PSTR 65                 // padded smem row stride (float2 elems)
#define ZPB  8                  // z-planes per box_wh block

// Scratch (no cudaMalloc allowed)
__device__ float2 g_p [TOT];    // (qk, qkv) bit-exact proj output (fixup source)
__device__ float2 g_t2[TOT];    // after w+h passes
__device__ int    g_cnt;
__device__ int    g_fixlist[MAXFIX];

__global__ void reset_kernel() { g_cnt = 0; }
__global__ void noop_kernel() {}

// ---------------------------------------------------------------------------
// Stage 1: per-voxel projections — R8/R16 instruction stream VERBATIM; only
// change is __launch_bounds__(128, 2): raises the ptxas register budget to
// 256/thread so the full live set (mf[64] + f[64] + working ~ 210 regs) stays
// in registers with ZERO spill (R16 allocated 164 and spilled ~45 -> LDL on
// the binding L1tex pipe). 2 blocks/SM instead of 3.
// aq/ak as one packed fma.rn.f32x2 chain (each lane IEEE fp32 -> bit-identical
// to scalar sequential ascending-c chains); av as scalar FFMA chain.
// qk = q*k; qkv = qk*v single roundings. g_p bit-exactness is load-bearing
// for near-zero denominators (see fixup).
// ---------------------------------------------------------------------------
__global__ __launch_bounds__(128, 2) void proj_kernel(
    const float* __restrict__ mov, const float* __restrict__ fix,
    const float* __restrict__ qw,  const float* __restrict__ kw,
    const float* __restrict__ vw)
{
    __shared__ float2 swqk[NC*NC];   // (wq, wk) interleaved, 32 KB
    __shared__ float  swv [NC*NC];   // 16 KB
    const int tid = threadIdx.x;
    for (int i = tid; i < NC*NC; i += 128) {
        swqk[i] = make_float2(qw[i], kw[i]);
        swv[i]  = vw[i];
    }
    __syncthreads();

    const int gid = blockIdx.x * 128 + tid;     // 0 .. NB*NVOX-1
    const int b   = (gid >= NVOX) ? 1 : 0;
    const int n   = gid - b * NVOX;

    const float* mp = mov + (long)b*NC*NVOX + n;
    const float* fp = fix + (long)b*NC*NVOX + n;

    unsigned long long mf[NC];   // packed (m[c], f[c])
    float f[NC];
    #pragma unroll
    for (int c = 0; c < NC; c++) {
        const float mv = mp[(long)c*NVOX];
        const float fv = fp[(long)c*NVOX];
        f[c] = fv;
        asm("mov.b64 %0, {%1,%2};" : "=l"(mf[c]) : "f"(mv), "f"(fv));
    }

    float2* op = g_p + (long)b*NC*NVOX + n;

    for (int l = 0; l < NC; l++) {
        const ulonglong2* wrow = (const ulonglong2*)(swqk + (l<<6));
        const float4*     vrow = (const float4*)(swv + (l<<6));
        unsigned long long aqk = 0ull;   // lanes: (aq, ak)
        float av = 0.f;
        #pragma unroll
        for (int j = 0; j < NC/4; j++) {
            const ulonglong2 wa = wrow[2*j];      // c = 4j, 4j+1
            const ulonglong2 wb = wrow[2*j+1];    // c = 4j+2, 4j+3
            const float4 wv4 = vrow[j];
            asm("fma.rn.f32x2 %0, %1, %2, %0;" : "+l"(aqk) : "l"(wa.x), "l"(mf[4*j+0]));
            av = __fmaf_rn(wv4.x, f[4*j+0], av);
            asm("fma.rn.f32x2 %0, %1, %2, %0;" : "+l"(aqk) : "l"(wa.y), "l"(mf[4*j+1]));
            av = __fmaf_rn(wv4.y, f[4*j+1], av);
            asm("fma.rn.f32x2 %0, %1, %2, %0;" : "+l"(aqk) : "l"(wb.x), "l"(mf[4*j+2]));
            av = __fmaf_rn(wv4.z, f[4*j+2], av);
            asm("fma.rn.f32x2 %0, %1, %2, %0;" : "+l"(aqk) : "l"(wb.y), "l"(mf[4*j+3]));
            av = __fmaf_rn(wv4.w, f[4*j+3], av);
        }
        float aq, ak;
        asm("mov.b64 {%0,%1}, %2;" : "=f"(aq), "=f"(ak) : "l"(aqk));
        const float qk  = __fmul_rn(aq, ak);
        const float qkv = __fmul_rn(qk, av);
        op[(long)l*NVOX] = make_float2(qk, qkv);
    }
}

// ---------------------------------------------------------------------------
// Stage 2ab (fused, software-pipelined): W then H box sums — R9 VERBATIM
// (measured 112us, DRAM 55%).
// ---------------------------------------------------------------------------
__global__ __launch_bounds__(256) void box_wh_kernel()
{
    extern __shared__ float2 smp[];
    float2* P = smp;               // [64][PSTR] current input plane
    float2* Q = smp + D*PSTR;      // [64][PSTR] after w-pass

    const int tid  = threadIdx.x;
    const int z0   = blockIdx.x * ZPB;
    const int chan = blockIdx.y;
    const long cb  = (long)chan*NVOX;

    for (int i = tid; i < D*D; i += 256)
        P[(i >> 6)*PSTR + (i & 63)] = g_p[cb + (long)z0*(D*D) + i];
    __syncthreads();

    #pragma unroll 1
    for (int p = 0; p < ZPB; p++) {
        const long nb = cb + (long)(z0 + p + 1)*(D*D);
        const bool pf = (p + 1 < ZPB);
        float2 rA[8], rB[8];

        if (pf) {
            #pragma unroll
            for (int k = 0; k < 8; k++) rA[k] = g_p[nb + k*256 + tid];
        }

        // w-pass: P -> Q
        {
            const int h   = tid & 63;
            const int w0  = (tid >> 6) * 16;
            const float2* row = P + h*PSTR;
            float2* qrow = Q + h*PSTR;
            float sx = 0.f, sy = 0.f;
            const int j0 = (w0 >= 4) ? (w0 - 4) : 0;
            for (int j = j0; j < w0 + 4; j++) { sx += row[j].x; sy += row[j].y; }
            #pragma unroll
            for (int i = 0; i < 16; i++) {
                const int w = w0 + i;
                if (w + 4 < D) { sx += row[w+4].x; sy += row[w+4].y; }
                qrow[w] = make_float2(sx, sy);
                if (w >= 4) { sx -= row[w-4].x; sy -= row[w-4].y; }
            }
        }
        __syncthreads();

        if (pf) {
            #pragma unroll
            for (int k = 0; k < 8; k++) rB[k] = g_p[nb + (k+8)*256 + tid];
        }

        // h-pass: Q -> g_t2
        {
            const int w   = tid & 63;
            const int h0  = (tid >> 6) * 16;
            const long pbase = cb + (long)(z0 + p)*(D*D);
            float sx = 0.f, sy = 0.f;
            const int j0 = (h0 >= 4) ? (h0 - 4) : 0;
            for (int j = j0; j < h0 + 4; j++) {
                const float2 v = Q[j*PSTR + w];
                sx += v.x; sy += v.y;
            }
            #pragma unroll
            for (int i = 0; i < 16; i++) {
                const int h = h0 + i;
                if (h + 4 < D) {
                    const float2 v = Q[(h+4)*PSTR + w];
                    sx += v.x; sy += v.y;
                }
                g_t2[pbase + h*D + w] = make_float2(sx, sy);
                if (h >= 4) {
                    const float2 v = Q[(h-4)*PSTR + w];
                    sx -= v.x; sy -= v.y;
                }
            }
        }

        if (pf) {
            #pragma unroll
            for (int k = 0; k < 8; k++) {
                const int i = k*256 + tid;
                P[(i >> 6)*PSTR + (i & 63)] = rA[k];
            }
            #pragma unroll
            for (int k = 0; k < 8; k++) {
                const int i = (k+8)*256 + tid;
                P[(i >> 6)*PSTR + (i & 63)] = rB[k];
            }
        }
        __syncthreads();
    }
}

// ---------------------------------------------------------------------------
// Stage 2c: box sum along Z + division + flagging — R9 VERBATIM (108us).
// ---------------------------------------------------------------------------
__global__ __launch_bounds__(256) void box_z_div_kernel(float* __restrict__ out)
{
    const int t    = threadIdx.x;
    const int wp   = t & 31;
    const int h    = blockIdx.x * 8 + (t >> 5);
    const int chan = blockIdx.y;
    const long ebase = (long)chan*NVOX + (long)h*D + 2*wp;
    const long base  = ebase >> 1;
    const float4* src = (const float4*)g_t2;
    float2*       o2  = (float2*)out;

    float4 ring[9];
    float4 s = make_float4(0.f, 0.f, 0.f, 0.f);
    #pragma unroll
    for (int j = 0; j < 4; j++) {
        float4 v = src[base + (long)j*(D*D/2)];
        ring[j % 9] = v;
        s.x += v.x; s.y += v.y; s.z += v.z; s.w += v.w;
    }
    #pragma unroll
    for (int i = 0; i < D; i++) {
        const int j = i + 4;
        if (j < D) {
            float4 v = src[base + (long)j*(D*D/2)];
            ring[j % 9] = v;
            s.x += v.x; s.y += v.y; s.z += v.z; s.w += v.w;
        }
        const long eidx = ebase + (long)i*(D*D);
        o2[eidx >> 1] = make_float2(__fdiv_rn(s.y, s.x), __fdiv_rn(s.w, s.z));
        if (fabsf(s.x) < FIX_T) {
            int slot = atomicAdd(&g_cnt, 1);
            if (slot < MAXFIX) g_fixlist[slot] = (int)eidx;
        }
        if (fabsf(s.z) < FIX_T) {
            int slot = atomicAdd(&g_cnt, 1);
            if (slot < MAXFIX) g_fixlist[slot] = (int)(eidx + 1);
        }
        const int j2 = i - 4;
        if (j2 >= 0) {
            float4 v = ring[j2 % 9];
            s.x -= v.x; s.y -= v.y; s.z -= v.z; s.w -= v.w;
        }
    }
}

// ---------------------------------------------------------------------------
// Stage 3: exact fixup, MLP-optimized — R16 VERBATIM. Same sequential
// ascending-(z,h,w) in-bounds fp32 fold as the reference; OOB w-taps load
// +0.0f (exact IEEE identity under RN with +0-seeded accumulator).
// ---------------------------------------------------------------------------
__global__ __launch_bounds__(256) void fixup_kernel(float* __restrict__ out)
{
    int cnt = g_cnt; if (cnt > MAXFIX) cnt = MAXFIX;
    for (int idx = blockIdx.x*256 + threadIdx.x; idx < cnt; idx += gridDim.x*256) {
        const int v    = g_fixlist[idx];
        const int chan = v >> 18;
        const int rem  = v & (NVOX-1);
        const int z = rem >> 12;
        const int h = (rem >> 6) & 63;
        const int w = rem & 63;
        const long cb = (long)chan*NVOX;

        float sD = 0.f, sN = 0.f;
        #pragma unroll 1
        for (int dz = z-4; dz <= z+4; dz++) {
            if ((unsigned)dz >= (unsigned)D) continue;   // skip OOB plane (no adds)
            const float2* plane = g_p + cb + (long)dz*(D*D);
            #pragma unroll 3
            for (int dh = h-4; dh <= h+4; dh++) {
                if ((unsigned)dh < (unsigned)D) {
                    const float2* row = plane + (long)dh*D;
                    float2 t[9];
                    #pragma unroll
                    for (int k = 0; k < 9; k++) {
                        const int dw = w - 4 + k;
                        t[k] = ((unsigned)dw < (unsigned)D) ? row[dw]
                                                            : make_float2(0.f, 0.f);
                    }
                    #pragma unroll
                    for (int k = 0; k < 9; k++) {
                        sD = __fadd_rn(sD, t[k].x);
                        sN = __fadd_rn(sN, t[k].y);
                    }
                }
            }
        }
        out[v] = __fdiv_rn(sN, sD);
    }
}

extern "C" void kernel_launch(void* const* d_in, const int* in_sizes, int n_in,
                              void* d_out, int out_size) {
    (void)in_sizes; (void)n_in; (void)out_size;
    const float* mov = (const float*)d_in[0];
    const float* fix = (const float*)d_in[1];
    const float* qw  = (const float*)d_in[2];
    const float* kw  = (const float*)d_in[3];
    const float* vw  = (const float*)d_in[4];
    float* out = (float*)d_out;

    const int wh_smem = 2*D*PSTR * sizeof(float2);      // 66560 B
    cudaFuncSetAttribute(box_wh_kernel,
                         cudaFuncAttributeMaxDynamicSharedMemorySize, wh_smem);

    reset_kernel<<<1, 1>>>();                           // 0
    noop_kernel<<<1, 32>>>();                           // 1
    noop_kernel<<<1, 32>>>();                           // 2
    proj_kernel<<<(NB*NVOX)/128, 128>>>(mov, fix, qw, kw, vw);   // 3 (captured)
    box_wh_kernel<<<dim3(D/ZPB, NCH), 256, wh_smem>>>();
    box_z_div_kernel<<<dim3(8, NCH), 256>>>(out);
    fixup_kernel<<<512, 256>>>(out);
}